// round 14
// baseline (speedup 1.0000x reference)
#include <cuda_runtime.h>

// Shape: [1, 8, 8, 8, 258, 258, 1] fp32; 512 images of 258x258.
// 34,080,768 elems = 8,520,192 float4 chunks = 33,282 block-tiles of 256.
//
// Persistent grid-stride variant of R13: 1216 resident CTAs stride over the
// 33,282 tiles (~28 iters each), removing CTA launch/retire churn.
// Per tile: block-uniform edge test brem = (tile*1024) % 66564;
//   edge (brem < 258 or > 65280)  -> __noinline__ slow path (R10 logic)
//   else fast path: ONE divmod (idx % 258) + in-chunk permutes
//     (258 % 4 == 2: w0==0 lane0<-v.y; w0==254 lane3<-v.z;
//      w0==256 straddle lane1<-v.x, lane2<-v.w)

#define HW        258u
#define IMG_ELEMS 66564u
#define NTILES    33282u
#define GRID      1216u     // 152 SMs * 8 CTAs

__device__ __noinline__ static void halo_slow_tile(
    const float* __restrict__ x,
    const float4* __restrict__ hm,
    float4* __restrict__ out,
    unsigned i)
{
    unsigned idx = i * 4u;

    float4 v  = __ldcs(reinterpret_cast<const float4*>(x + idx));
    float4 bm = __ldcs(hm + i);

    unsigned rem = idx % IMG_ELEMS;
    unsigned w0  = rem % HW;

    bool e0  = (w0 == 0u);
    bool e4  = (w0 == HW - 4u);
    bool s   = (w0 == HW - 2u);
    bool top = (rem < HW);
    bool bot = (rem >= 66306u);        // 257*258
    bool sb  = (rem == 66304u);        // straddle into row 257
    bool tb  = top | bot;

    float u0 = 0.f, u1 = 0.f, u2 = 0.f, u3 = 0.f;
    if (tb | sb) {
        int D = top ? (int)HW : -(int)HW;
        const float* p = x + (int)idx + D;
        float2 ua = *reinterpret_cast<const float2*>(p);
        float2 ub = *reinterpret_cast<const float2*>(p + 2);
        u0 = ua.x; u1 = ua.y; u2 = ub.x; u3 = ub.y;
    }

    float a0 = e0 ? v.y : (tb ? u0 : v.x);
    float a1 = s  ? v.x : (tb ? u1 : v.y);
    float a2 = s  ? v.w : (tb ? u2 : v.z);
    float a3 = e4 ? v.z : ((s ? sb : tb) ? u3 : v.w);

    float4 r;
    r.x = a0 * bm.x;
    r.y = a1 * bm.y;
    r.z = a2 * bm.z;
    r.w = a3 * bm.w;
    __stcs(out + i, r);
}

__global__ __launch_bounds__(256)
void halo_persist_kernel(const float* __restrict__ x,
                         const float4* __restrict__ hm,
                         float4* __restrict__ out)
{
    for (unsigned tile = blockIdx.x; tile < NTILES; tile += GRID) {
        unsigned i = tile * 256u + threadIdx.x;

        unsigned brem = (tile * 1024u) % IMG_ELEMS;   // block-uniform
        if (brem < HW || brem > 65280u) {
            halo_slow_tile(x, hm, out, i);
            continue;
        }

        unsigned idx = i * 4u;
        float4 v  = __ldcs(reinterpret_cast<const float4*>(x + idx));
        float4 bm = __ldcs(hm + i);

        unsigned w0 = idx % HW;   // 0..256, even — only per-thread divmod

        float a0 = (w0 == 0u)      ? v.y : v.x;
        float a1 = (w0 == HW - 2u) ? v.x : v.y;
        float a2 = (w0 == HW - 2u) ? v.w : v.z;
        float a3 = (w0 == HW - 4u) ? v.z : v.w;

        float4 r;
        r.x = a0 * bm.x;
        r.y = a1 * bm.y;
        r.z = a2 * bm.z;
        r.w = a3 * bm.w;
        __stcs(out + i, r);
    }
}

extern "C" void kernel_launch(void* const* d_in, const int* in_sizes, int n_in,
                              void* d_out, int out_size)
{
    const float* x  = (const float*)d_in[0];
    const float* hm = (const float*)d_in[1];
    float* out = (float*)d_out;

    halo_persist_kernel<<<GRID, 256>>>(x, (const float4*)hm, (float4*)out);
}

// round 15
// speedup vs baseline: 1.0502x; 1.0502x over previous
#include <cuda_runtime.h>

// Shape: [1, 8, 8, 8, 258, 258, 1] fp32; 512 images of 258x258.
// 34,080,768 elems = 8,520,192 float4 chunks; grid 16641 x 512 exact.
//
// R13 structure (best: 61.6us), block size 512 instead of 256.
// Fast path (96%+ of blocks), ONE per-thread divmod:
//   w0 = idx % 258 (66564 = 258^2 -> image offset vanishes mod 258)
//   258 % 4 == 2 -> w-edge sources are in-chunk permutes:
//     w0==0: lane0<-v.y   w0==254: lane3<-v.z   w0==256: lane1<-v.x, lane2<-v.w
// Edge blocks (block-uniform test, slow path sealed behind __noinline__ so
// ptxas cannot hoist the mod-66564 into the fast stream):
//   brem = (b*2048) % 66564; edge iff brem < 258 or brem > 64256
//   (covers top rows, bottom rows incl. straddle chunk at rem 66304, and
//    blocks wrapping an image boundary — slow path is position-general).

#define HW        258u
#define IMG_ELEMS 66564u
#define TOTAL4    8520192u
#define BLK       512u
#define GRID      16641u      // TOTAL4 / BLK exact

__device__ __noinline__ static void halo_slow_chunk(
    const float* __restrict__ x,
    const float4* __restrict__ hm,
    float4* __restrict__ out,
    unsigned i)
{
    unsigned idx = i * 4u;

    float4 v  = __ldcs(reinterpret_cast<const float4*>(x + idx));
    float4 bm = __ldcs(hm + i);

    unsigned rem = idx % IMG_ELEMS;
    unsigned w0  = rem % HW;

    bool e0  = (w0 == 0u);
    bool e4  = (w0 == HW - 4u);
    bool s   = (w0 == HW - 2u);
    bool top = (rem < HW);
    bool bot = (rem >= 66306u);        // 257*258
    bool sb  = (rem == 66304u);        // straddle into row 257
    bool tb  = top | bot;

    float u0 = 0.f, u1 = 0.f, u2 = 0.f, u3 = 0.f;
    if (tb | sb) {
        int D = top ? (int)HW : -(int)HW;
        const float* p = x + (int)idx + D;
        float2 ua = *reinterpret_cast<const float2*>(p);
        float2 ub = *reinterpret_cast<const float2*>(p + 2);
        u0 = ua.x; u1 = ua.y; u2 = ub.x; u3 = ub.y;
    }

    float a0 = e0 ? v.y : (tb ? u0 : v.x);
    float a1 = s  ? v.x : (tb ? u1 : v.y);
    float a2 = s  ? v.w : (tb ? u2 : v.z);
    float a3 = e4 ? v.z : ((s ? sb : tb) ? u3 : v.w);

    float4 r;
    r.x = a0 * bm.x;
    r.y = a1 * bm.y;
    r.z = a2 * bm.z;
    r.w = a3 * bm.w;
    __stcs(out + i, r);
}

__global__ __launch_bounds__(512)
void halo_call512_kernel(const float* __restrict__ x,
                         const float4* __restrict__ hm,
                         float4* __restrict__ out)
{
    unsigned b = blockIdx.x;
    unsigned i = b * BLK + threadIdx.x;   // exact cover

    // Block-uniform edge test; slow path sealed behind a call.
    unsigned brem = (b * (BLK * 4u)) % IMG_ELEMS;
    if (brem < HW || brem > 64256u) {     // 66304 - 2048
        halo_slow_chunk(x, hm, out, i);
        return;
    }

    // ---- fast path: pure 1-divmod branchless stream ----
    unsigned idx = i * 4u;
    float4 v  = __ldcs(reinterpret_cast<const float4*>(x + idx));
    float4 bm = __ldcs(hm + i);

    unsigned w0 = idx % HW;   // 0..256, even

    float a0 = (w0 == 0u)      ? v.y : v.x;
    float a1 = (w0 == HW - 2u) ? v.x : v.y;
    float a2 = (w0 == HW - 2u) ? v.w : v.z;
    float a3 = (w0 == HW - 4u) ? v.z : v.w;

    float4 r;
    r.x = a0 * bm.x;
    r.y = a1 * bm.y;
    r.z = a2 * bm.z;
    r.w = a3 * bm.w;
    __stcs(out + i, r);
}

extern "C" void kernel_launch(void* const* d_in, const int* in_sizes, int n_in,
                              void* d_out, int out_size)
{
    const float* x  = (const float*)d_in[0];
    const float* hm = (const float*)d_in[1];
    float* out = (float*)d_out;

    halo_call512_kernel<<<GRID, BLK>>>(x, (const float4*)hm, (float4*)out);
}

// round 16
// speedup vs baseline: 1.0583x; 1.0077x over previous
#include <cuda_runtime.h>

// Shape: [1, 8, 8, 8, 258, 258, 1] fp32; 512 images of 258x258.
// total = 34,080,768 elems = 8,520,192 float4 chunks = 33282 blocks x 256 EXACT.
//
// FINAL kernel (R6 structure — best measured: 56.19us kernel / 61.6us total,
// HBM 6.62 TB/s = ~100% of the empirically established 2R/1W stream ceiling).
//
// Key fact: 258 % 4 == 2, so every w-edge element shares its 16B chunk with
// its remap source -> w-edge remap is a register permute of the loaded v:
//   w0==0   chunk (w 0..3):     lane0 <- v.y   (x[h][1])
//   w0==254 chunk (w 254..257): lane3 <- v.z   (x[h][256])
//   w0==256 straddle (h:256,257 / h+1:0,1): lane1 <- v.x, lane2 <- v.w
// Only rows h==0 / h==257 (plus the straddle into row 257) need real extra
// loads; those chunks live in ~1.7% of warps -> short divergent path with 4
// scalar loads at idx+k+delta (delta = +-1 w-edge w/ ORIGINAL h, +-258 h-edge;
// w-axis assigns run last in the reference, so the w-rule wins at corners).

#define HW        258
#define IMG_ELEMS 66564u      // 258*258
#define TOTAL4    8520192u    // float4 chunks

__global__ __launch_bounds__(256)
void halo_final_kernel(const float* __restrict__ x,
                       const float4* __restrict__ hm,
                       float4* __restrict__ out)
{
    unsigned i = blockIdx.x * 256u + threadIdx.x;   // exact cover, no guard
    unsigned idx = i * 4u;

    float4 v = __ldcs(reinterpret_cast<const float4*>(x + idx));
    float4 b = __ldcs(hm + i);

    unsigned rem = idx % IMG_ELEMS;
    unsigned h0  = rem / (unsigned)HW;
    unsigned w0  = rem - h0 * (unsigned)HW;    // even, 0..256

    float a0 = v.x, a1 = v.y, a2 = v.z, a3 = v.w;

    // h-edge slow path: chunk touches row 0 or row 257.
    if (h0 == 0u || h0 == HW - 1u || (h0 == HW - 2u && w0 == HW - 2u)) {
        unsigned h = h0, w = w0;
        float lane[4];
#pragma unroll
        for (int k = 0; k < 4; ++k) {
            int delta = 0;
            if (w == 0u)           delta = 1;      // w-edge keeps original h
            else if (w == HW - 1u) delta = -1;
            else if (h == 0u)      delta = HW;     // h-edge
            else if (h == HW - 1u) delta = -HW;
            lane[k] = __ldg(x + (int)(idx + k) + delta);
            if (++w == HW) { w = 0u; ++h; }
        }
        a0 = lane[0]; a1 = lane[1]; a2 = lane[2]; a3 = lane[3];
    } else {
        // Branchless w-edge permutes (predicated selects).
        if (w0 == 0u)           a0 = v.y;          // (h,0)   <- x[h][1]
        if (w0 == HW - 4u)      a3 = v.z;          // (h,257) <- x[h][256]
        if (w0 == HW - 2u) {                       // straddle chunk
            a1 = v.x;                              // (h,257) <- x[h][256]
            a2 = v.w;                              // (h+1,0) <- x[h+1][1]
        }
    }

    float4 r;
    r.x = a0 * b.x;
    r.y = a1 * b.y;
    r.z = a2 * b.z;
    r.w = a3 * b.w;
    __stcs(out + i, r);
}

extern "C" void kernel_launch(void* const* d_in, const int* in_sizes, int n_in,
                              void* d_out, int out_size)
{
    const float* x  = (const float*)d_in[0];
    const float* hm = (const float*)d_in[1];
    float* out = (float*)d_out;

    halo_final_kernel<<<TOTAL4 / 256u, 256>>>(x, (const float4*)hm, (float4*)out);
}

// round 17
// speedup vs baseline: 1.0660x; 1.0073x over previous
#include <cuda_runtime.h>

// Shape: [1, 8, 8, 8, 258, 258, 1] fp32; 512 images of 258x258.
// 34,080,768 elems = 8,520,192 float4 chunks; grid 33282 x 256 exact.
//
// FINAL (= R13, best measured total 61.6us; kernel 56.4us @ 6.60 TB/s, which
// nine structural variants established as the chip's 2R/1W stream ceiling).
//
// Single launch, block-uniform specialization with a __noinline__ slow path
// so ptxas cannot hoist the mod-66564 into the fast stream.
//
// Fast path (97.7% of blocks), ONE per-thread divmod:
//   w0 = idx % 258 (66564 = 258^2 -> image offset vanishes mod 258)
//   258 % 4 == 2 -> w-edge sources are in-chunk permutes:
//     w0==0: lane0<-v.y   w0==254: lane3<-v.z   w0==256: lane1<-v.x, lane2<-v.w
//
// Edge blocks: brem = (b*1024) % 66564 in [0,258) or (65280, 66564).
// Slow path (per-corner verified; w-rule wins at corners with ORIGINAL h):
//   top=(rem<258) bot=(rem>=66306) sb=(rem==66304) tb=top|bot
//   u = x[idx+D .. +3], D = +258 (top) / -258 (bot/sb), via 2x 8B loads
//   lane0=e0?v.y:tb?u0:v.x   lane1=s?v.x:tb?u1:v.y
//   lane2=s?v.w:tb?u2:v.z    lane3=e4?v.z:(s?sb:tb)?u3:v.w

#define HW        258u
#define IMG_ELEMS 66564u
#define TOTAL4    8520192u

__device__ __noinline__ static void halo_slow_block(
    const float* __restrict__ x,
    const float4* __restrict__ hm,
    float4* __restrict__ out,
    unsigned i)
{
    unsigned idx = i * 4u;

    float4 v  = __ldcs(reinterpret_cast<const float4*>(x + idx));
    float4 bm = __ldcs(hm + i);

    unsigned rem = idx % IMG_ELEMS;
    unsigned w0  = rem % HW;

    bool e0  = (w0 == 0u);
    bool e4  = (w0 == HW - 4u);
    bool s   = (w0 == HW - 2u);
    bool top = (rem < HW);
    bool bot = (rem >= 66306u);        // 257*258
    bool sb  = (rem == 66304u);        // straddle into row 257
    bool tb  = top | bot;

    float u0 = 0.f, u1 = 0.f, u2 = 0.f, u3 = 0.f;
    if (tb | sb) {
        int D = top ? (int)HW : -(int)HW;
        const float* p = x + (int)idx + D;
        float2 ua = *reinterpret_cast<const float2*>(p);
        float2 ub = *reinterpret_cast<const float2*>(p + 2);
        u0 = ua.x; u1 = ua.y; u2 = ub.x; u3 = ub.y;
    }

    float a0 = e0 ? v.y : (tb ? u0 : v.x);
    float a1 = s  ? v.x : (tb ? u1 : v.y);
    float a2 = s  ? v.w : (tb ? u2 : v.z);
    float a3 = e4 ? v.z : ((s ? sb : tb) ? u3 : v.w);

    float4 r;
    r.x = a0 * bm.x;
    r.y = a1 * bm.y;
    r.z = a2 * bm.z;
    r.w = a3 * bm.w;
    __stcs(out + i, r);
}

__global__ __launch_bounds__(256)
void halo_call_kernel(const float* __restrict__ x,
                      const float4* __restrict__ hm,
                      float4* __restrict__ out)
{
    unsigned b = blockIdx.x;
    unsigned i = b * 256u + threadIdx.x;   // exact cover

    // Block-uniform edge test; slow path sealed behind a call.
    unsigned brem = (b * 1024u) % IMG_ELEMS;
    if (brem < HW || brem > 65280u) {
        halo_slow_block(x, hm, out, i);
        return;
    }

    // ---- fast path: pure 1-divmod branchless stream ----
    unsigned idx = i * 4u;
    float4 v  = __ldcs(reinterpret_cast<const float4*>(x + idx));
    float4 bm = __ldcs(hm + i);

    unsigned w0 = idx % HW;   // 0..256, even

    float a0 = (w0 == 0u)      ? v.y : v.x;
    float a1 = (w0 == HW - 2u) ? v.x : v.y;
    float a2 = (w0 == HW - 2u) ? v.w : v.z;
    float a3 = (w0 == HW - 4u) ? v.z : v.w;

    float4 r;
    r.x = a0 * bm.x;
    r.y = a1 * bm.y;
    r.z = a2 * bm.z;
    r.w = a3 * bm.w;
    __stcs(out + i, r);
}

extern "C" void kernel_launch(void* const* d_in, const int* in_sizes, int n_in,
                              void* d_out, int out_size)
{
    const float* x  = (const float*)d_in[0];
    const float* hm = (const float*)d_in[1];
    float* out = (float*)d_out;

    halo_call_kernel<<<TOTAL4 / 256u, 256>>>(x, (const float4*)hm, (float4*)out);
}